// round 2
// baseline (speedup 1.0000x reference)
#include <cuda_runtime.h>
#include <math.h>

#define B_    64
#define HID   1536
#define NH    12
#define NKV   2
#define HD    128
#define G_    6
#define INTER 8960
#define MAXB  256
#define BSZ   16
#define NBLK  16384
#define QSZ   1536
#define KVSZ  256
#define QKVN  2048
#define EPS_  1e-6f
#define SCALE 0.08838834764831845f   // 1/sqrt(128)

// ---------------- scratch (device globals; no allocation allowed) ----------
__device__ float g_res1[B_*HID];
__device__ float g_hn  [B_*HID];
__device__ float g_hn2 [B_*HID];
__device__ float g_qkv [B_*QKVN];
__device__ float g_attn[B_*QSZ];
__device__ float g_tmp [B_*HID];
__device__ float g_gu  [B_*2*INTER];
__device__ float g_act [B_*INTER];
__device__ float g_part[8*B_*QKVN];   // split-K partials (max 8*64*2048)

// ---------------- fused add + RMSNorm -------------------------------------
__global__ void __launch_bounds__(256)
addnorm_kernel(const float* __restrict__ x, const float* __restrict__ y,
               const float* __restrict__ w,
               float* __restrict__ res, float* __restrict__ nout)
{
    int b = blockIdx.x, tid = threadIdx.x;
    const float* xr = x + b*HID;
    const float* yr = y + b*HID;
    float v[6];
    float ss = 0.f;
#pragma unroll
    for (int t = 0; t < 6; t++) {
        int i = tid + t*256;
        float s = xr[i] + yr[i];
        v[t] = s;
        ss += s*s;
    }
    __shared__ float red[8];
#pragma unroll
    for (int o = 16; o; o >>= 1) ss += __shfl_xor_sync(~0u, ss, o);
    if ((tid & 31) == 0) red[tid >> 5] = ss;
    __syncthreads();
    if (tid < 8) {
        float t2 = red[tid];
#pragma unroll
        for (int o = 4; o; o >>= 1) t2 += __shfl_xor_sync(0xffu, t2, o);
        if (tid == 0) red[0] = t2;
    }
    __syncthreads();
    float inv = rsqrtf(red[0] * (1.0f/HID) + EPS_);
#pragma unroll
    for (int t = 0; t < 6; t++) {
        int i = tid + t*256;
        res[b*HID + i]  = v[t];
        nout[b*HID + i] = v[t] * inv * w[i];
    }
}

// ---------------- tiled SGEMM: C[64,N] = A[64,K] @ B[K,N] ------------------
// grid.x tiles N by 64; grid.y = split-K index (klen rows each); output
// written to C + blockIdx.y*64*N (reduced later when gridDim.y > 1).
__global__ void __launch_bounds__(256)
gemm64(const float* __restrict__ A, const float* __restrict__ B,
       float* __restrict__ C, int K, int N, int klen)
{
    __shared__ float As[16][64];
    __shared__ float Bs[16][64];
    const int tid = threadIdx.x;
    const int n0  = blockIdx.x * 64;
    const int k0  = blockIdx.y * klen;
    float* Cp = C + (size_t)blockIdx.y * 64 * N;

    const int am = tid >> 2;            // 0..63 (A row)
    const int ak = (tid & 3) * 4;       // A k sub-offset
    const int br = tid >> 4;            // 0..15 (B k row)
    const int bc = (tid & 15) * 4;      // B col sub-offset
    const int tr = tid >> 4;            // 0..15 (output row group)
    const int tc = tid & 15;            // 0..15 (output col group)

    float acc[4][4] = {};
    for (int kt = 0; kt < klen; kt += 16) {
        float4 av = *(const float4*)(A + (size_t)am*K + k0 + kt + ak);
        float4 bv = *(const float4*)(B + (size_t)(k0 + kt + br)*N + n0 + bc);
        __syncthreads();
        As[ak+0][am] = av.x; As[ak+1][am] = av.y;
        As[ak+2][am] = av.z; As[ak+3][am] = av.w;
        *(float4*)&Bs[br][bc] = bv;
        __syncthreads();
#pragma unroll
        for (int kk = 0; kk < 16; kk++) {
            float4 a = *(const float4*)&As[kk][tr*4];
            float4 bq = *(const float4*)&Bs[kk][tc*4];
            acc[0][0] += a.x*bq.x; acc[0][1] += a.x*bq.y; acc[0][2] += a.x*bq.z; acc[0][3] += a.x*bq.w;
            acc[1][0] += a.y*bq.x; acc[1][1] += a.y*bq.y; acc[1][2] += a.y*bq.z; acc[1][3] += a.y*bq.w;
            acc[2][0] += a.z*bq.x; acc[2][1] += a.z*bq.y; acc[2][2] += a.z*bq.z; acc[2][3] += a.z*bq.w;
            acc[3][0] += a.w*bq.x; acc[3][1] += a.w*bq.y; acc[3][2] += a.w*bq.z; acc[3][3] += a.w*bq.w;
        }
    }
#pragma unroll
    for (int i = 0; i < 4; i++) {
        float4 o = make_float4(acc[i][0], acc[i][1], acc[i][2], acc[i][3]);
        *(float4*)(Cp + (size_t)(tr*4 + i)*N + n0 + tc*4) = o;
    }
}

// ---------------- split-K reduce (+ optional bias) -------------------------
__global__ void __launch_bounds__(256)
reduce_kernel(const float* __restrict__ part, const float* __restrict__ bias,
              float* __restrict__ out, int MN, int N, int S)
{
    int i = blockIdx.x*256 + threadIdx.x;
    if (i >= MN) return;
    float s = bias ? bias[i % N] : 0.f;
    for (int p = 0; p < S; p++) s += part[(size_t)p*MN + i];
    out[i] = s;
}

// ---------------- NEOX RoPE (in place on q & k of qkv) ---------------------
__global__ void __launch_bounds__(256)
rope_kernel(float* __restrict__ qkv, const int* __restrict__ positions)
{
    int b = blockIdx.x;
    float pos = (float)positions[b];
    for (int idx = threadIdx.x; idx < (NH + NKV)*64; idx += 256) {
        int head = idx >> 6, d = idx & 63;
        float inv = powf(1.0e6f, -(float)d * (1.0f/64.0f));
        float ang = pos * inv;
        float s, c;
        sincosf(ang, &s, &c);
        float* p = qkv + b*QKVN + (head < NH ? head*HD : QSZ + (head - NH)*HD);
        float x1 = p[d], x2 = p[d+64];
        p[d]    = x1*c - x2*s;
        p[d+64] = x2*c + x1*s;
    }
}

// ---------------- GQA paged decode attention -------------------------------
// block = (b, kv_head). 8 warps stride the key sequence; each warp keeps
// online-softmax state for the 6 query heads entirely in registers
// (4 floats/lane of HD=128). The new token's k/v (slot == slot_mapping[b])
// is substituted at read time; the cache input is never written.
__global__ void __launch_bounds__(256)
attn_kernel(const float* __restrict__ qkv, const float* __restrict__ kvc,
            const int* __restrict__ bt_all, const int* __restrict__ slot_map,
            const int* __restrict__ seq_lens, float* __restrict__ out)
{
    const int b    = blockIdx.x >> 1;
    const int kvh  = blockIdx.x & 1;
    const int warp = threadIdx.x >> 5;
    const int lane = threadIdx.x & 31;
    const int len  = seq_lens[b];
    const int smap = slot_map[b];
    const int* bt  = bt_all + b*MAXB;

    const float* kc   = kvc;
    const float* vc   = kvc + (size_t)NBLK*BSZ*NKV*HD;
    const float* knew = qkv + b*QKVN + QSZ + kvh*HD;
    const float* vnew = qkv + b*QKVN + QSZ + KVSZ + kvh*HD;

    float q[G_][4];
#pragma unroll
    for (int h = 0; h < G_; h++) {
        float4 qv = *(const float4*)(qkv + b*QKVN + (kvh*G_ + h)*HD + lane*4);
        q[h][0] = qv.x*SCALE; q[h][1] = qv.y*SCALE;
        q[h][2] = qv.z*SCALE; q[h][3] = qv.w*SCALE;
    }

    float m[G_], l[G_], acc[G_][4];
#pragma unroll
    for (int h = 0; h < G_; h++) {
        m[h] = -1e30f; l[h] = 0.f;
        acc[h][0] = acc[h][1] = acc[h][2] = acc[h][3] = 0.f;
    }

    // prefetch first key/value for this warp
    float4 kf = make_float4(0,0,0,0), vf = kf;
    {
        int j = warp;
        if (j < len) {
            int slot = bt[j >> 4]*BSZ + (j & 15);
            const float *kp, *vp;
            if (slot == smap) { kp = knew; vp = vnew; }
            else {
                size_t off = ((size_t)slot*NKV + kvh)*HD;
                kp = kc + off; vp = vc + off;
            }
            kf = *(const float4*)(kp + lane*4);
            vf = *(const float4*)(vp + lane*4);
        }
    }

    for (int j = warp; j < len; j += 8) {
        float4 kfn = kf, vfn = vf;
        int jn = j + 8;
        if (jn < len) {
            int slot = bt[jn >> 4]*BSZ + (jn & 15);
            const float *kp, *vp;
            if (slot == smap) { kp = knew; vp = vnew; }
            else {
                size_t off = ((size_t)slot*NKV + kvh)*HD;
                kp = kc + off; vp = vc + off;
            }
            kfn = *(const float4*)(kp + lane*4);
            vfn = *(const float4*)(vp + lane*4);
        }

        float s[G_];
#pragma unroll
        for (int h = 0; h < G_; h++)
            s[h] = q[h][0]*kf.x + q[h][1]*kf.y + q[h][2]*kf.z + q[h][3]*kf.w;
#pragma unroll
        for (int o = 16; o; o >>= 1) {
#pragma unroll
            for (int h = 0; h < G_; h++)
                s[h] += __shfl_xor_sync(~0u, s[h], o);
        }
#pragma unroll
        for (int h = 0; h < G_; h++) {
            if (s[h] > m[h]) {   // warp-uniform branch (s, m identical on all lanes)
                float corr = __expf(m[h] - s[h]);
                l[h] = l[h]*corr + 1.f;
                acc[h][0] = acc[h][0]*corr + vf.x;
                acc[h][1] = acc[h][1]*corr + vf.y;
                acc[h][2] = acc[h][2]*corr + vf.z;
                acc[h][3] = acc[h][3]*corr + vf.w;
                m[h] = s[h];
            } else {
                float p = __expf(s[h] - m[h]);
                l[h] += p;
                acc[h][0] += p*vf.x;
                acc[h][1] += p*vf.y;
                acc[h][2] += p*vf.z;
                acc[h][3] += p*vf.w;
            }
        }
        kf = kfn; vf = vfn;
    }

    // combine 8 warps (logsumexp merge)
    __shared__ float s_acc[8][G_][HD];
    __shared__ float s_m[8][G_], s_l[8][G_], s_w[8][G_], s_L[G_];
#pragma unroll
    for (int h = 0; h < G_; h++) {
        s_acc[warp][h][lane*4+0] = acc[h][0];
        s_acc[warp][h][lane*4+1] = acc[h][1];
        s_acc[warp][h][lane*4+2] = acc[h][2];
        s_acc[warp][h][lane*4+3] = acc[h][3];
        if (lane == 0) { s_m[warp][h] = m[h]; s_l[warp][h] = l[h]; }
    }
    __syncthreads();
    if (threadIdx.x < G_) {
        int h = threadIdx.x;
        float M = -1e30f;
#pragma unroll
        for (int w = 0; w < 8; w++) M = fmaxf(M, s_m[w][h]);
        float L = 0.f;
#pragma unroll
        for (int w = 0; w < 8; w++) {
            float wt = __expf(s_m[w][h] - M);
            s_w[w][h] = wt;
            L += wt * s_l[w][h];
        }
        s_L[h] = 1.f / L;
    }
    __syncthreads();
    for (int idx = threadIdx.x; idx < G_*HD; idx += 256) {
        int h = idx >> 7, d = idx & 127;
        float o = 0.f;
#pragma unroll
        for (int w = 0; w < 8; w++) o += s_w[w][h] * s_acc[w][h][d];
        out[b*QSZ + (kvh*G_ + h)*HD + d] = o * s_L[h];
    }
}

// ---------------- SwiGLU activation ----------------------------------------
__global__ void __launch_bounds__(256)
act_kernel(const float* __restrict__ gu, float* __restrict__ out)
{
    int i = blockIdx.x*256 + threadIdx.x;
    if (i >= B_*INTER) return;
    int b = i / INTER, c = i - b*INTER;
    float g = gu[(size_t)b*2*INTER + c];
    float u = gu[(size_t)b*2*INTER + INTER + c];
    out[i] = (g / (1.f + __expf(-g))) * u;
}

// ---------------- launch ----------------------------------------------------
extern "C" void kernel_launch(void* const* d_in, const int* in_sizes, int n_in,
                              void* d_out, int out_size)
{
    const int*   positions    = (const int*)  d_in[0];
    const float* hidden       = (const float*)d_in[1];
    const float* residual     = (const float*)d_in[2];
    const float* kv_cache     = (const float*)d_in[3];
    const int*   block_tables = (const int*)  d_in[4];
    const int*   slot_mapping = (const int*)  d_in[5];
    const int*   seq_lens     = (const int*)  d_in[6];
    // d_in[7] = is_prefill (statically 0)
    const float* w_qkv = (const float*)d_in[8];
    const float* b_qkv = (const float*)d_in[9];
    const float* w_o   = (const float*)d_in[10];
    const float* ln1   = (const float*)d_in[11];
    const float* ln2   = (const float*)d_in[12];
    const float* w_gu  = (const float*)d_in[13];
    const float* w_dn  = (const float*)d_in[14];
    float* out = (float*)d_out;   // [h (B*HID) | res2 (B*HID)]

    float *res1, *hn, *hn2, *qkv, *attn, *tmp, *gu, *act, *part;
    cudaGetSymbolAddress((void**)&res1, g_res1);
    cudaGetSymbolAddress((void**)&hn,   g_hn);
    cudaGetSymbolAddress((void**)&hn2,  g_hn2);
    cudaGetSymbolAddress((void**)&qkv,  g_qkv);
    cudaGetSymbolAddress((void**)&attn, g_attn);
    cudaGetSymbolAddress((void**)&tmp,  g_tmp);
    cudaGetSymbolAddress((void**)&gu,   g_gu);
    cudaGetSymbolAddress((void**)&act,  g_act);
    cudaGetSymbolAddress((void**)&part, g_part);

    // 1. res1 = hidden + residual ; hn = rmsnorm(res1)*ln1
    addnorm_kernel<<<B_, 256>>>(hidden, residual, ln1, res1, hn);

    // 2. qkv = hn @ w_qkv + b_qkv   (split-K 4)
    gemm64<<<dim3(QKVN/64, 4), 256>>>(hn, w_qkv, part, HID, QKVN, HID/4);
    reduce_kernel<<<(B_*QKVN + 255)/256, 256>>>(part, b_qkv, qkv, B_*QKVN, QKVN, 4);

    // 3. RoPE on q, k (in place)
    rope_kernel<<<B_, 256>>>(qkv, positions);

    // 4. paged GQA decode attention
    attn_kernel<<<B_*NKV, 256>>>(qkv, kv_cache, block_tables, slot_mapping,
                                 seq_lens, attn);

    // 5. o-proj (split-K 4)
    gemm64<<<dim3(HID/64, 4), 256>>>(attn, w_o, part, QSZ, HID, QSZ/4);
    reduce_kernel<<<(B_*HID + 255)/256, 256>>>(part, nullptr, tmp, B_*HID, HID, 4);

    // 6. res2 = o + res1 (-> out second half) ; hn2 = rmsnorm(res2)*ln2
    addnorm_kernel<<<B_, 256>>>(tmp, res1, ln2, out + B_*HID, hn2);

    // 7. gate_up GEMM (N=17920, no split)
    gemm64<<<dim3(2*INTER/64, 1), 256>>>(hn2, w_gu, gu, HID, 2*INTER, HID);

    // 8. SwiGLU
    act_kernel<<<(B_*INTER + 255)/256, 256>>>(gu, act);

    // 9. down GEMM (split-K 8) -> out first half
    gemm64<<<dim3(HID/64, 8), 256>>>(act, w_dn, part, INTER, HID, INTER/8);
    reduce_kernel<<<(B_*HID + 255)/256, 256>>>(part, nullptr, out, B_*HID, HID, 8);
}